// round 8
// baseline (speedup 1.0000x reference)
#include <cuda_runtime.h>
#include <cstdint>

#define B_   64
#define T_   1024
#define H_   512
#define I_   64
#define O_   8
#define ALPHA 0.2f
#define NSTD  0.05f

#define CL    8                 // cluster size
#define NBG   16                // batch groups
#define GRID  (CL*NBG)          // 128 CTAs, single wave
#define TPB   512
#define NB    4                 // batches per cluster
#define NC    64                // columns per CTA
#define KS    16                // k-slices (one per warp)

// operand buffer geometry (floats), batch-interleaved by k-pair:
//   h element (k,b)  -> (k>>1)*8 + b*2 + (k&1)
//   x element (i,b)  -> 2048 + (i>>1)*8 + b*2 + (i&1)
#define OPF   2304              // floats per buffer (8KB h + 1KB x)
#define XBASE 2048

// ---- packed f32x2 helpers (sm_100+) ----
__device__ __forceinline__ unsigned long long pk2(float lo, float hi) {
    unsigned long long v;
    asm("mov.b64 %0, {%1,%2};" : "=l"(v) : "f"(lo), "f"(hi));
    return v;
}
__device__ __forceinline__ void ffma2(unsigned long long& d,
                                      unsigned long long a,
                                      unsigned long long b) {
    asm("fma.rn.f32x2 %0, %1, %2, %0;" : "+l"(d) : "l"(a), "l"(b));
}
__device__ __forceinline__ float lo32(unsigned long long v) {
    return __uint_as_float((unsigned)(v & 0xffffffffu));
}
__device__ __forceinline__ float hi32(unsigned long long v) {
    return __uint_as_float((unsigned)(v >> 32));
}
__device__ __forceinline__ uint32_t smem_u32(const void* p) {
    uint32_t a;
    asm("{ .reg .u64 t; cvta.to.shared.u64 t, %1; cvt.u32.u64 %0, t; }"
        : "=r"(a) : "l"(p));
    return a;
}
__device__ __forceinline__ uint32_t mapa_rank(uint32_t laddr, uint32_t rank) {
    uint32_t ra;
    asm("mapa.shared::cluster.u32 %0, %1, %2;" : "=r"(ra) : "r"(laddr), "r"(rank));
    return ra;
}
__device__ __forceinline__ void st_async_b64(uint32_t raddr, unsigned long long v,
                                             uint32_t rmbar) {
    asm volatile(
        "st.async.shared::cluster.mbarrier::complete_tx::bytes.b64 [%0], %1, [%2];"
        :: "r"(raddr), "l"(v), "r"(rmbar) : "memory");
}
__device__ __forceinline__ void mbar_init(uint32_t mbar, uint32_t cnt) {
    asm volatile("mbarrier.init.shared.b64 [%0], %1;" :: "r"(mbar), "r"(cnt) : "memory");
}
__device__ __forceinline__ void mbar_expect_tx(uint32_t mbar, uint32_t bytes) {
    asm volatile("mbarrier.arrive.expect_tx.shared.b64 _, [%0], %1;"
                 :: "r"(mbar), "r"(bytes) : "memory");
}
__device__ __forceinline__ void mbar_wait(uint32_t mbar, uint32_t parity) {
    uint32_t done;
    asm volatile(
        "{ .reg .pred P;\n"
        "  mbarrier.try_wait.parity.acquire.cta.shared::cta.b64 P, [%1], %2;\n"
        "  selp.b32 %0, 1, 0, P; }"
        : "=r"(done) : "r"(mbar), "r"(parity) : "memory");
    if (!done) {
        asm volatile(
            "{ .reg .pred P;\n"
            "WL%=:\n"
            "  mbarrier.try_wait.parity.acquire.cta.shared::cta.b64 P, [%0], %1, 0x989680;\n"
            "  @P bra WD%=;\n"
            "  bra WL%=;\n"
            "WD%=: }"
            :: "r"(mbar), "r"(parity) : "memory");
    }
}
__device__ __forceinline__ void cluster_sync() {
    asm volatile("barrier.cluster.arrive.aligned;" ::: "memory");
    asm volatile("barrier.cluster.wait.aligned;" ::: "memory");
}

// profiling alignment: capture lands on launch index 3 (0-based)
extern "C" __global__ void knop() {}

extern "C" __global__ void __launch_bounds__(TPB, 1) __cluster_dims__(CL, 1, 1)
rnn_main(const float* __restrict__ input, const float* __restrict__ noise,
         const float* __restrict__ wi, const float* __restrict__ si,
         const float* __restrict__ wrec, const float* __restrict__ bias,
         const float* __restrict__ wi_mask, const float* __restrict__ wrec_mask,
         const float* __restrict__ h0, float* __restrict__ traj)
{
    __shared__ __align__(16) float s_op[2][OPF];             // 18 KB operands
    __shared__ __align__(16) float s_red[NB][KS][NC];        // 16 KB f32 partials
    __shared__ __align__(8)  unsigned long long s_mbar[2 * CL]; // [buffer][src rank]

    const int tid  = threadIdx.x;
    const int rank = blockIdx.x % CL;     // column tile
    const int bg   = blockIdx.x / CL;     // batch group
    const int C0   = rank * NC;
    const int B0   = bg * NB;

    // compute-role: 32 column-threads (2 cols each) x 16 k-slices (1/warp)
    const int ct   = tid & 31;
    const int ksub = tid >> 5;            // warp-uniform
    const int c0   = C0 + ct * 2;         // my even column
    const int c1   = c0 + 1;

    // finalize-role (tid < 256): (batch, col)
    const int fb = tid >> 6;
    const int fc = tid & 63;
    const int gb = B0 + fb;
    const int gc = C0 + fc;

    // -------- preload effective weights: 18 k-pairs x 2 cols ---------------
    // wrec pairs: k0 = ksub*32 + 2*pp (pp<16); wi pairs: i0 = ksub*4 + 2*pp (pp<2)
    unsigned long long wA[18], wB[18];    // 72 registers
#pragma unroll
    for (int pp = 0; pp < 16; pp++) {
        int k0 = ksub * 32 + 2 * pp;
        float a0 = fabsf(wrec[(size_t)k0 * H_ + c0]) * wrec_mask[(size_t)k0 * H_ + c0];
        float a1 = fabsf(wrec[(size_t)(k0 + 1) * H_ + c0]) * wrec_mask[(size_t)(k0 + 1) * H_ + c0];
        float b0 = fabsf(wrec[(size_t)k0 * H_ + c1]) * wrec_mask[(size_t)k0 * H_ + c1];
        float b1 = fabsf(wrec[(size_t)(k0 + 1) * H_ + c1]) * wrec_mask[(size_t)(k0 + 1) * H_ + c1];
        wA[pp] = pk2(a0, a1);
        wB[pp] = pk2(b0, b1);
    }
#pragma unroll
    for (int pp = 0; pp < 2; pp++) {
        int i0 = ksub * 4 + 2 * pp;
        float a0 = wi[(size_t)i0 * H_ + c0] * si[i0] * wi_mask[(size_t)i0 * H_ + c0];
        float a1 = wi[(size_t)(i0 + 1) * H_ + c0] * si[i0 + 1] * wi_mask[(size_t)(i0 + 1) * H_ + c0];
        float b0 = wi[(size_t)i0 * H_ + c1] * si[i0] * wi_mask[(size_t)i0 * H_ + c1];
        float b1 = wi[(size_t)(i0 + 1) * H_ + c1] * si[i0 + 1] * wi_mask[(size_t)(i0 + 1) * H_ + c1];
        wA[16 + pp] = pk2(a0, a1);
        wB[16 + pp] = pk2(b0, b1);
    }

    const uint32_t s_op_u32  = smem_u32(&s_op[0][0]);
    const uint32_t mbar_u32  = smem_u32(&s_mbar[0]);
    // my two wait barriers: (buffer, src rank = ksub>>1)
    const uint32_t wbar0 = mbar_u32 + 8u * (0 * CL + (ksub >> 1));
    const uint32_t wbar1 = mbar_u32 + 8u * (1 * CL + (ksub >> 1));

    const float fbias = (tid < 256) ? bias[gc] : 0.f;
    // my send destination float offset inside every CTA's s_op h-region
    const uint32_t dst_off = (uint32_t)(((gc >> 1) * 8 + fb * 2) * 4);

    // incremented pointers
    const float* nz_p = noise + ((size_t)gb * T_) * H_ + gc;            // += H_
    const float* x_p  = input + ((size_t)(B0 + ((tid >> 5) & 3)) * T_) * I_
                              + ((tid & 31) * 2);                        // += I_
    float*       tr_p = traj + ((size_t)gb * (T_ + 1)) * H_ + gc;       // += H_

    // -------- init ---------------------------------------------------------
    if (tid == 0) {
#pragma unroll
        for (int m = 0; m < 2 * CL; m++) mbar_init(mbar_u32 + 8u * m, 1u);
    }
    float h_prev = 0.f;
    if (tid < 256) {
        h_prev = h0[gc];
        *tr_p = h_prev;
        tr_p += H_;
    }
    // stage relu(h0) into buffer 0 (interleaved layout)
#pragma unroll
    for (int q = 0; q < 4; q++) {
        int e = tid * 4 + q;              // [0,2048)
        int pairidx = e >> 3, half = e & 1;
        int k = pairidx * 2 + half;
        s_op[0][e] = fmaxf(h0[k], 0.f) * 0.f + fmaxf(h0[k], 0.f); // keep simple
    }
    // (rewrite cleanly: e encodes (pairidx, b, half) exactly as layout index)
    if (tid >= 256 && tid < 384) {
        int xb = (tid >> 5) & 3, xi = (tid & 31) * 2;
        float2 xv = *(const float2*)x_p;
        *(float2*)&s_op[0][XBASE + (xi >> 1) * 8 + xb * 2] = xv;
        x_p += I_;
    }
    __syncthreads();
    cluster_sync();   // mbarriers + buffer0 visible cluster-wide

    int p = 0;
    uint32_t ph0 = 0, ph1 = 0;
    for (int t = 0; t < T_; t++) {
        const int pn = p ^ 1;

        // ---- prefetch ------------------------------------------------------
        float nz = 0.f;
        if (tid < 256) { nz = *nz_p; nz_p += H_; }
        float2 xnext = make_float2(0.f, 0.f);
        if (tid >= 256 && tid < 384 && t + 1 < T_) {
            xnext = *(const float2*)x_p; x_p += I_;
        }

        // post expectations for next buffer's 8 per-rank barriers
        if (tid < 8 && t + 1 < T_)
            mbar_expect_tx(mbar_u32 + 8u * (pn * CL + tid), 1024u);

        // ---- per-warp wait: only my source rank's block --------------------
        if (t > 0) {
            if (p == 0) { mbar_wait(wbar0, ph0); ph0 ^= 1; }
            else        { mbar_wait(wbar1, ph1); ph1 ^= 1; }
        }

        // ---- matmul: 18 k-pairs x 4 batches x 2 cols -----------------------
        const float* ob = &s_op[p][0];
        unsigned long long accA[NB], accB[NB];
#pragma unroll
        for (int b = 0; b < NB; b++) { accA[b] = 0ULL; accB[b] = 0ULL; }

#pragma unroll
        for (int pp = 0; pp < 16; pp++) {
            const int P = (ksub << 4) + pp;          // global wrec pair
            ulonglong2 v01 = *(const ulonglong2*)&ob[P << 3];
            ulonglong2 v23 = *(const ulonglong2*)&ob[(P << 3) + 4];
            ffma2(accA[0], v01.x, wA[pp]);
            ffma2(accA[1], v01.y, wA[pp]);
            ffma2(accA[2], v23.x, wA[pp]);
            ffma2(accA[3], v23.y, wA[pp]);
            ffma2(accB[0], v01.x, wB[pp]);
            ffma2(accB[1], v01.y, wB[pp]);
            ffma2(accB[2], v23.x, wB[pp]);
            ffma2(accB[3], v23.y, wB[pp]);
        }
#pragma unroll
        for (int pp = 0; pp < 2; pp++) {
            const int P = (ksub << 1) + pp;          // global wi pair
            ulonglong2 v01 = *(const ulonglong2*)&ob[XBASE + (P << 3)];
            ulonglong2 v23 = *(const ulonglong2*)&ob[XBASE + (P << 3) + 4];
            ffma2(accA[0], v01.x, wA[16 + pp]);
            ffma2(accA[1], v01.y, wA[16 + pp]);
            ffma2(accA[2], v23.x, wA[16 + pp]);
            ffma2(accA[3], v23.y, wA[16 + pp]);
            ffma2(accB[0], v01.x, wB[16 + pp]);
            ffma2(accB[1], v01.y, wB[16 + pp]);
            ffma2(accB[2], v23.x, wB[16 + pp]);
            ffma2(accB[3], v23.y, wB[16 + pp]);
        }

        // collapse packed halves to f32 and store partials
#pragma unroll
        for (int b = 0; b < NB; b++) {
            float2 pr = make_float2(lo32(accA[b]) + hi32(accA[b]),
                                    lo32(accB[b]) + hi32(accB[b]));
            *(float2*)&s_red[b][ksub][ct * 2] = pr;
        }

        // stage x_{t+1} into next buffer (local x region)
        if (tid >= 256 && tid < 384) {
            int xb = (tid >> 5) & 3, xi = (tid & 31) * 2;
            *(float2*)&s_op[pn][XBASE + (xi >> 1) * 8 + xb * 2] = xnext;
        }
        __syncthreads();                  // bar1: partials + x staging visible

        // ---- finalize: reduce 16 slices, h update, traj, sends -------------
        if (tid < 256) {
            float s = 0.f;
#pragma unroll
            for (int ks = 0; ks < KS; ks++) s += s_red[fb][ks][fc];

            float h_new = h_prev + NSTD * nz + ALPHA * (-h_prev + s + fbias);
            float rv = fmaxf(h_new, 0.f);
            float rv_hi = __shfl_down_sync(0xffffffffu, rv, 1);
            float hn_hi = __shfl_down_sync(0xffffffffu, h_new, 1);
            if ((fc & 1) == 0) {
                if (t + 1 < T_) {
                    unsigned long long hv = pk2(rv, rv_hi);
                    uint32_t doff = (uint32_t)pn * (OPF * 4) + dst_off;
                    uint32_t moff = 8u * (uint32_t)(pn * CL + rank);
#pragma unroll
                    for (int r = 0; r < CL; r++) {
                        uint32_t ra = mapa_rank(s_op_u32, (uint32_t)r) + doff;
                        uint32_t rm = mapa_rank(mbar_u32, (uint32_t)r) + moff;
                        st_async_b64(ra, hv, rm);
                    }
                }
                *(float2*)tr_p = make_float2(h_new, hn_hi);
            }
            tr_p += H_;
            h_prev = h_new;
        }
        __syncthreads();                  // bar2: s_red WAR protection

        p = pn;
    }

    cluster_sync();   // no CTA exits while peers' st.async may target it
}

// output pass: out[b,t,o] = relu(traj[b,t+1,:]) @ wo_eff
extern "C" __global__ void __launch_bounds__(256)
rnn_out(const float* __restrict__ traj, const float* __restrict__ wo,
        const float* __restrict__ so, const float* __restrict__ wo_mask,
        float* __restrict__ out)
{
    __shared__ float s_wo[O_][H_];
    const int tid = threadIdx.x;
    for (int i = tid; i < H_ * O_; i += 256) {
        int c = i / O_, o = i % O_;
        s_wo[o][c] = wo[i] * so[o] * wo_mask[i];
    }
    __syncthreads();

    const int warp = tid >> 5, lane = tid & 31;
    const size_t row = (size_t)blockIdx.x * 8 + warp;   // b*T + t
    const int b = (int)(row >> 10);
    const int t = (int)(row & 1023);
    const float* tp = traj + ((size_t)b * (T_ + 1) + t + 1) * H_;

    float acc[O_];
#pragma unroll
    for (int o = 0; o < O_; o++) acc[o] = 0.f;

    for (int ccb = 0; ccb < H_; ccb += 32) {
        float r = fmaxf(tp[ccb + lane], 0.f);
#pragma unroll
        for (int o = 0; o < O_; o++) acc[o] += r * s_wo[o][ccb + lane];
    }
#pragma unroll
    for (int off = 16; off; off >>= 1)
#pragma unroll
        for (int o = 0; o < O_; o++)
            acc[o] += __shfl_down_sync(0xffffffffu, acc[o], off);
    if (lane == 0) {
#pragma unroll
        for (int o = 0; o < O_; o++) out[row * O_ + o] = acc[o];
    }
}

extern "C" void kernel_launch(void* const* d_in, const int* in_sizes, int n_in,
                              void* d_out, int out_size)
{
    (void)in_sizes; (void)n_in; (void)out_size;
    const float* input = (const float*)d_in[0];
    const float* noise = (const float*)d_in[1];
    const float* wi    = (const float*)d_in[2];
    const float* si    = (const float*)d_in[3];
    const float* wrec  = (const float*)d_in[4];
    const float* bias  = (const float*)d_in[5];
    const float* wo    = (const float*)d_in[6];
    const float* so    = (const float*)d_in[7];
    const float* wim   = (const float*)d_in[8];
    const float* wrm   = (const float*)d_in[9];
    const float* wom   = (const float*)d_in[10];
    const float* h0    = (const float*)d_in[11];

    float* out  = (float*)d_out;
    float* traj = out + (size_t)B_ * T_ * O_;   // [B, T+1, H] after [B, T, O]

    // 3 no-op launches: aim ncu capture (launch idx 3) at rnn_main
    for (int i = 0; i < 3; i++) knop<<<1, 32>>>();

    rnn_main<<<GRID, TPB>>>(input, noise, wi, si, wrec, bias,
                            wim, wrm, h0, traj);
    rnn_out<<<(B_ * T_) / 8, 256>>>(traj, wo, so, wom, out);
}

// round 9
// speedup vs baseline: 1.2997x; 1.2997x over previous
#include <cuda_runtime.h>
#include <cstdint>

#define B_   64
#define T_   1024
#define H_   512
#define I_   64
#define O_   8
#define ALPHA 0.2f
#define NSTD  0.05f

#define CL    4                 // cluster size (column tiles)
#define GRID  128               // 32 clusters x 4 CTAs, single wave
#define TPB   512
#define NB    2                 // batches per cluster
#define NC    128               // columns per CTA
#define KS    4                 // k-slices (tid>>7, warp-uniform)
#define NPAIR 72                // k-pairs per thread: (128 wrec + 16 wi)/2
#define EXPBYTES 3072           // 3 remote 1KB blocks per buffer per step

// operand buffer geometry (floats), 2-batch interleave by k-pair:
//   h element (k,b) -> (k>>1)*4 + b*2 + (k&1)       [0, 1024)
//   x element (i,b) -> 1024 + (i>>1)*4 + b*2 + (i&1) [1024, 1152)
#define OPF   1152
#define XBASE 1024

// ---- packed f32x2 helpers (sm_100+) ----
__device__ __forceinline__ unsigned long long pk2(float lo, float hi) {
    unsigned long long v;
    asm("mov.b64 %0, {%1,%2};" : "=l"(v) : "f"(lo), "f"(hi));
    return v;
}
__device__ __forceinline__ void ffma2(unsigned long long& d,
                                      unsigned long long a,
                                      unsigned long long b) {
    asm("fma.rn.f32x2 %0, %1, %2, %0;" : "+l"(d) : "l"(a), "l"(b));
}
__device__ __forceinline__ float lo32(unsigned long long v) {
    return __uint_as_float((unsigned)(v & 0xffffffffu));
}
__device__ __forceinline__ float hi32(unsigned long long v) {
    return __uint_as_float((unsigned)(v >> 32));
}
__device__ __forceinline__ uint32_t smem_u32(const void* p) {
    uint32_t a;
    asm("{ .reg .u64 t; cvta.to.shared.u64 t, %1; cvt.u32.u64 %0, t; }"
        : "=r"(a) : "l"(p));
    return a;
}
__device__ __forceinline__ uint32_t mapa_rank(uint32_t laddr, uint32_t rank) {
    uint32_t ra;
    asm("mapa.shared::cluster.u32 %0, %1, %2;" : "=r"(ra) : "r"(laddr), "r"(rank));
    return ra;
}
__device__ __forceinline__ void st_async_b64(uint32_t raddr, unsigned long long v,
                                             uint32_t rmbar) {
    asm volatile(
        "st.async.shared::cluster.mbarrier::complete_tx::bytes.b64 [%0], %1, [%2];"
        :: "r"(raddr), "l"(v), "r"(rmbar) : "memory");
}
__device__ __forceinline__ void mbar_init(uint32_t mbar, uint32_t cnt) {
    asm volatile("mbarrier.init.shared.b64 [%0], %1;" :: "r"(mbar), "r"(cnt) : "memory");
}
__device__ __forceinline__ void mbar_expect_tx(uint32_t mbar, uint32_t bytes) {
    asm volatile("mbarrier.arrive.expect_tx.shared.b64 _, [%0], %1;"
                 :: "r"(mbar), "r"(bytes) : "memory");
}
__device__ __forceinline__ void mbar_wait(uint32_t mbar, uint32_t parity) {
    uint32_t done;
    asm volatile(
        "{ .reg .pred P;\n"
        "  mbarrier.try_wait.parity.acquire.cta.shared::cta.b64 P, [%1], %2;\n"
        "  selp.b32 %0, 1, 0, P; }"
        : "=r"(done) : "r"(mbar), "r"(parity) : "memory");
    if (!done) {
        asm volatile(
            "{ .reg .pred P;\n"
            "WL%=:\n"
            "  mbarrier.try_wait.parity.acquire.cta.shared::cta.b64 P, [%0], %1, 0x989680;\n"
            "  @P bra WD%=;\n"
            "  bra WL%=;\n"
            "WD%=: }"
            :: "r"(mbar), "r"(parity) : "memory");
    }
}
__device__ __forceinline__ void cluster_sync() {
    asm volatile("barrier.cluster.arrive.aligned;" ::: "memory");
    asm volatile("barrier.cluster.wait.aligned;" ::: "memory");
}

// profiling alignment: capture lands on launch index 3 (0-based)
extern "C" __global__ void knop() {}

extern "C" __global__ void __launch_bounds__(TPB, 1) __cluster_dims__(CL, 1, 1)
rnn_main(const float* __restrict__ input, const float* __restrict__ noise,
         const float* __restrict__ wi, const float* __restrict__ si,
         const float* __restrict__ wrec, const float* __restrict__ bias,
         const float* __restrict__ wi_mask, const float* __restrict__ wrec_mask,
         const float* __restrict__ h0, float* __restrict__ traj)
{
    __shared__ __align__(16) float s_op[2][OPF];          // 9 KB operands
    __shared__ __align__(16) float s_red[NB][KS][NC];     // 4 KB f32 partials
    __shared__ __align__(8)  unsigned long long s_mbar[2];

    const int tid  = threadIdx.x;
    const int rank = blockIdx.x % CL;     // column tile [0,4)
    const int bg   = blockIdx.x / CL;     // batch group [0,32)
    const int C0   = rank * NC;
    const int B0   = bg * NB;

    // compute-role: 128 column-threads x 4 k-slices (ksub = tid>>7, warp-uniform)
    const int ct   = tid & 127;
    const int ksub = tid >> 7;
    const int cc   = C0 + ct;
    const int kb   = ksub * (H_ / KS);    // 128 wrec k start
    const int ib   = ksub * (I_ / KS);    // 16 wi k start

    // finalize-role (tid < 256): batch b = tid>>7, column c = tid&127
    const int fb = tid >> 7;
    const int fc = tid & 127;
    const int gb = B0 + fb;
    const int gc = C0 + fc;

    // -------- preload effective weights: 72 packed (k,k+1) pairs, one col ---
    unsigned long long w2[NPAIR];
#pragma unroll
    for (int pp = 0; pp < 64; pp++) {
        int k0 = kb + 2 * pp;
        float a = fabsf(wrec[(size_t)k0 * H_ + cc]) * wrec_mask[(size_t)k0 * H_ + cc];
        float b = fabsf(wrec[(size_t)(k0 + 1) * H_ + cc]) * wrec_mask[(size_t)(k0 + 1) * H_ + cc];
        w2[pp] = pk2(a, b);
    }
#pragma unroll
    for (int pp = 64; pp < NPAIR; pp++) {
        int i0 = ib + 2 * (pp - 64);
        float a = wi[(size_t)i0 * H_ + cc] * si[i0] * wi_mask[(size_t)i0 * H_ + cc];
        float b = wi[(size_t)(i0 + 1) * H_ + cc] * si[i0 + 1] * wi_mask[(size_t)(i0 + 1) * H_ + cc];
        w2[pp] = pk2(a, b);
    }

    const uint32_t s_op_u32 = smem_u32(&s_op[0][0]);
    const uint32_t mbar_u32 = smem_u32(&s_mbar[0]);
    uint32_t peer_op[CL], peer_mb[CL];
#pragma unroll
    for (int r = 0; r < CL; r++) {
        peer_op[r] = mapa_rank(s_op_u32, (uint32_t)r);
        peer_mb[r] = mapa_rank(mbar_u32, (uint32_t)r);
    }
    // my (even-col) send destination byte offset within the h region
    const uint32_t dst_off = (uint32_t)(((fc >> 1) * 4 + fb * 2) * 4) + (uint32_t)(C0 * 8);

    const float fbias = (tid < 256) ? bias[gc] : 0.f;

    // incremented pointers
    const float* nz_p = noise + ((size_t)gb * T_) * H_ + gc;            // += H_
    const int xb = (tid >> 5) & 1, xi = (tid & 31) * 2;                 // for tid 256..319
    const float* x_p  = input + ((size_t)(B0 + xb) * T_) * I_ + xi;     // += I_
    float*       tr_p = traj + ((size_t)gb * (T_ + 1)) * H_ + gc;       // += H_

    // -------- init ----------------------------------------------------------
    if (tid == 0) { mbar_init(mbar_u32, 1u); mbar_init(mbar_u32 + 8, 1u); }
    float h_prev = 0.f;
    if (tid < 256) {
        h_prev = h0[gc];
        *tr_p = h_prev;
        tr_p += H_;
    }
    // stage relu(h0) into buffer 0 (interleaved layout): 1024 floats, 2/thread
#pragma unroll
    for (int q = 0; q < 2; q++) {
        int e = tid * 2 + q;              // [0,1024)
        int k = (e >> 2) * 2 + (e & 1);   // pairidx*2 + half
        s_op[0][e] = fmaxf(h0[k], 0.f);
    }
    // stage x_0 (tid 256..319)
    if (tid >= 256 && tid < 320) {
        float2 xv = *(const float2*)x_p;
        *(float2*)&s_op[0][XBASE + (xi >> 1) * 4 + xb * 2] = xv;
        x_p += I_;
    }
    __syncthreads();
    cluster_sync();   // mbarriers + buffer0 visible cluster-wide

    int p = 0;
    uint32_t ph0 = 0, ph1 = 0;
    for (int t = 0; t < T_; t++) {
        const int pn = p ^ 1;

        // ---- prefetch -------------------------------------------------------
        float nz = 0.f;
        if (tid < 256) { nz = *nz_p; nz_p += H_; }
        float2 xnext = make_float2(0.f, 0.f);
        if (tid >= 256 && tid < 320 && t + 1 < T_) {
            xnext = *(const float2*)x_p; x_p += I_;
        }

        if (tid == 0 && t + 1 < T_)
            mbar_expect_tx(mbar_u32 + 8u * pn, EXPBYTES);

        // ---- wait for this step's operands ---------------------------------
        if (t > 0) {
            if (p == 0) { mbar_wait(mbar_u32, ph0);     ph0 ^= 1; }
            else        { mbar_wait(mbar_u32 + 8, ph1); ph1 ^= 1; }
        }

        // ---- matmul: 72 k-pairs x 2 batches, 1 column ----------------------
        const float* ob = &s_op[p][0];
        unsigned long long a0 = 0ULL, a1 = 0ULL;
#pragma unroll
        for (int pp = 0; pp < 64; pp++) {
            const int P = (ksub << 6) + pp;          // global wrec pair
            ulonglong2 v = *(const ulonglong2*)&ob[P << 2];
            ffma2(a0, v.x, w2[pp]);
            ffma2(a1, v.y, w2[pp]);
        }
#pragma unroll
        for (int pp = 0; pp < 8; pp++) {
            const int P = (ksub << 3) + pp;          // global wi pair
            ulonglong2 v = *(const ulonglong2*)&ob[XBASE + (P << 2)];
            ffma2(a0, v.x, w2[64 + pp]);
            ffma2(a1, v.y, w2[64 + pp]);
        }
        // collapse packed halves -> f32 partials
        s_red[0][ksub][ct] = lo32(a0) + hi32(a0);
        s_red[1][ksub][ct] = lo32(a1) + hi32(a1);

        // stage x_{t+1} into next buffer (local x region)
        if (tid >= 256 && tid < 320) {
            *(float2*)&s_op[pn][XBASE + (xi >> 1) * 4 + xb * 2] = xnext;
        }
        __syncthreads();                  // bar1: partials + x staging visible

        // ---- finalize: sum 4 slices, h update, traj, sends ------------------
        if (tid < 256) {
            float s = s_red[fb][0][fc] + s_red[fb][1][fc]
                    + s_red[fb][2][fc] + s_red[fb][3][fc];

            float h_new = h_prev + NSTD * nz + ALPHA * (-h_prev + s + fbias);
            float rv = fmaxf(h_new, 0.f);
            float rv_hi = __shfl_down_sync(0xffffffffu, rv, 1);
            float hn_hi = __shfl_down_sync(0xffffffffu, h_new, 1);
            if ((fc & 1) == 0) {
                if (t + 1 < T_) {
                    unsigned long long hv = pk2(rv, rv_hi);
                    uint32_t doff = (uint32_t)pn * (OPF * 4) + dst_off;
                    uint32_t moff = 8u * (uint32_t)pn;
                    // own block: plain local store (visible after bar2)
                    *(float2*)((char*)s_op + doff) = make_float2(rv, rv_hi);
#pragma unroll
                    for (int r = 0; r < CL; r++) {
                        if (r != rank)
                            st_async_b64(peer_op[r] + doff, hv, peer_mb[r] + moff);
                    }
                }
                *(float2*)tr_p = make_float2(h_new, hn_hi);
            }
            tr_p += H_;
            h_prev = h_new;
        }
        __syncthreads();                  // bar2: s_red WAR + local h visible

        p = pn;
    }

    cluster_sync();   // no CTA exits while peers' st.async may target it
}

// output pass: out[b,t,o] = relu(traj[b,t+1,:]) @ wo_eff
extern "C" __global__ void __launch_bounds__(256)
rnn_out(const float* __restrict__ traj, const float* __restrict__ wo,
        const float* __restrict__ so, const float* __restrict__ wo_mask,
        float* __restrict__ out)
{
    __shared__ float s_wo[O_][H_];
    const int tid = threadIdx.x;
    for (int i = tid; i < H_ * O_; i += 256) {
        int c = i / O_, o = i % O_;
        s_wo[o][c] = wo[i] * so[o] * wo_mask[i];
    }
    __syncthreads();

    const int warp = tid >> 5, lane = tid & 31;
    const size_t row = (size_t)blockIdx.x * 8 + warp;   // b*T + t
    const int b = (int)(row >> 10);
    const int t = (int)(row & 1023);
    const float* tp = traj + ((size_t)b * (T_ + 1) + t + 1) * H_;

    float acc[O_];
#pragma unroll
    for (int o = 0; o < O_; o++) acc[o] = 0.f;

    for (int ccb = 0; ccb < H_; ccb += 32) {
        float r = fmaxf(tp[ccb + lane], 0.f);
#pragma unroll
        for (int o = 0; o < O_; o++) acc[o] += r * s_wo[o][ccb + lane];
    }
#pragma unroll
    for (int off = 16; off; off >>= 1)
#pragma unroll
        for (int o = 0; o < O_; o++)
            acc[o] += __shfl_down_sync(0xffffffffu, acc[o], off);
    if (lane == 0) {
#pragma unroll
        for (int o = 0; o < O_; o++) out[row * O_ + o] = acc[o];
    }
}

extern "C" void kernel_launch(void* const* d_in, const int* in_sizes, int n_in,
                              void* d_out, int out_size)
{
    (void)in_sizes; (void)n_in; (void)out_size;
    const float* input = (const float*)d_in[0];
    const float* noise = (const float*)d_in[1];
    const float* wi    = (const float*)d_in[2];
    const float* si    = (const float*)d_in[3];
    const float* wrec  = (const float*)d_in[4];
    const float* bias  = (const float*)d_in[5];
    const float* wo    = (const float*)d_in[6];
    const float* so    = (const float*)d_in[7];
    const float* wim   = (const float*)d_in[8];
    const float* wrm   = (const float*)d_in[9];
    const float* wom   = (const float*)d_in[10];
    const float* h0    = (const float*)d_in[11];

    float* out  = (float*)d_out;
    float* traj = out + (size_t)B_ * T_ * O_;   // [B, T+1, H] after [B, T, O]

    // 3 no-op launches: aim ncu capture (launch idx 3) at rnn_main
    for (int i = 0; i < 3; i++) knop<<<1, 32>>>();

    rnn_main<<<GRID, TPB>>>(input, noise, wi, si, wrec, bias,
                            wim, wrm, h0, traj);
    rnn_out<<<(B_ * T_) / 8, 256>>>(traj, wo, so, wom, out);
}

// round 10
// speedup vs baseline: 1.4647x; 1.1269x over previous
#include <cuda_runtime.h>
#include <cstdint>

#define B_   64
#define T_   1024
#define H_   512
#define I_   64
#define O_   8
#define ALPHA 0.2f
#define NSTD  0.05f

#define CL    4                 // cluster size (column tiles)
#define GRID  128               // 32 clusters x 4 CTAs, single wave
#define TPB   512
#define NB    2                 // batches per cluster
#define NC    128               // columns per CTA
#define KS    4                 // k-slices (tid>>7, warp-uniform)
#define NREG  44                // weight pairs kept in registers
#define NSW   28                // weight pairs in smem (20 wrec + 8 wi)
#define EXPBYTES 4096           // 4 x 1KB h blocks (incl own) per buffer
#define MBCOUNT 65              // 64 x-thread arrivals + 1 expect_tx arrival

// operand buffer geometry (floats), 2-batch interleave by k-pair:
//   h element (k,b) -> (k>>1)*4 + b*2 + (k&1)        [0, 1024)
//   x element (i,b) -> 1024 + (i>>1)*4 + b*2 + (i&1) [1024, 1152)
#define OPF   1152
#define XBASE 1024

// dynamic smem layout (bytes)
#define OFF_OP   0              // float [2][OPF]           = 9216
#define OFF_RED  9216           // float [2][NB][KS][NC]    = 8192
#define OFF_MBAR 17408          // u64 [2]                  = 16
#define OFF_SW   17536          // u64 [NSW][TPB]           = 114688
#define SMEM_TOTAL (OFF_SW + NSW * TPB * 8)

// ---- packed f32x2 helpers (sm_100+) ----
__device__ __forceinline__ unsigned long long pk2(float lo, float hi) {
    unsigned long long v;
    asm("mov.b64 %0, {%1,%2};" : "=l"(v) : "f"(lo), "f"(hi));
    return v;
}
__device__ __forceinline__ void ffma2(unsigned long long& d,
                                      unsigned long long a,
                                      unsigned long long b) {
    asm("fma.rn.f32x2 %0, %1, %2, %0;" : "+l"(d) : "l"(a), "l"(b));
}
__device__ __forceinline__ float lo32(unsigned long long v) {
    return __uint_as_float((unsigned)(v & 0xffffffffu));
}
__device__ __forceinline__ float hi32(unsigned long long v) {
    return __uint_as_float((unsigned)(v >> 32));
}
__device__ __forceinline__ uint32_t smem_u32(const void* p) {
    uint32_t a;
    asm("{ .reg .u64 t; cvta.to.shared.u64 t, %1; cvt.u32.u64 %0, t; }"
        : "=r"(a) : "l"(p));
    return a;
}
__device__ __forceinline__ uint32_t mapa_rank(uint32_t laddr, uint32_t rank) {
    uint32_t ra;
    asm("mapa.shared::cluster.u32 %0, %1, %2;" : "=r"(ra) : "r"(laddr), "r"(rank));
    return ra;
}
__device__ __forceinline__ void st_async_b64(uint32_t raddr, unsigned long long v,
                                             uint32_t rmbar) {
    asm volatile(
        "st.async.shared::cluster.mbarrier::complete_tx::bytes.b64 [%0], %1, [%2];"
        :: "r"(raddr), "l"(v), "r"(rmbar) : "memory");
}
__device__ __forceinline__ void mbar_init(uint32_t mbar, uint32_t cnt) {
    asm volatile("mbarrier.init.shared.b64 [%0], %1;" :: "r"(mbar), "r"(cnt) : "memory");
}
__device__ __forceinline__ void mbar_expect_tx(uint32_t mbar, uint32_t bytes) {
    asm volatile("mbarrier.arrive.expect_tx.shared.b64 _, [%0], %1;"
                 :: "r"(mbar), "r"(bytes) : "memory");
}
__device__ __forceinline__ void mbar_arrive(uint32_t mbar) {
    asm volatile("mbarrier.arrive.release.cta.shared.b64 _, [%0];"
                 :: "r"(mbar) : "memory");
}
__device__ __forceinline__ void mbar_wait(uint32_t mbar, uint32_t parity) {
    uint32_t done;
    asm volatile(
        "{ .reg .pred P;\n"
        "  mbarrier.try_wait.parity.acquire.cta.shared::cta.b64 P, [%1], %2;\n"
        "  selp.b32 %0, 1, 0, P; }"
        : "=r"(done) : "r"(mbar), "r"(parity) : "memory");
    if (!done) {
        asm volatile(
            "{ .reg .pred P;\n"
            "WL%=:\n"
            "  mbarrier.try_wait.parity.acquire.cta.shared::cta.b64 P, [%0], %1, 0x989680;\n"
            "  @P bra WD%=;\n"
            "  bra WL%=;\n"
            "WD%=: }"
            :: "r"(mbar), "r"(parity) : "memory");
    }
}
__device__ __forceinline__ void cluster_sync() {
    asm volatile("barrier.cluster.arrive.aligned;" ::: "memory");
    asm volatile("barrier.cluster.wait.aligned;" ::: "memory");
}

// profiling alignment: capture lands on launch index 3 (0-based)
extern "C" __global__ void knop() {}

extern "C" __global__ void __launch_bounds__(TPB, 1) __cluster_dims__(CL, 1, 1)
rnn_main(const float* __restrict__ input, const float* __restrict__ noise,
         const float* __restrict__ wi, const float* __restrict__ si,
         const float* __restrict__ wrec, const float* __restrict__ bias,
         const float* __restrict__ wi_mask, const float* __restrict__ wrec_mask,
         const float* __restrict__ h0, float* __restrict__ traj)
{
    extern __shared__ __align__(16) char smem[];
    float* s_op  = (float*)(smem + OFF_OP);             // [2][OPF]
    float* s_rd  = (float*)(smem + OFF_RED);            // [2][NB][KS][NC]
    unsigned long long* s_w = (unsigned long long*)(smem + OFF_SW); // [NSW][TPB]

    const int tid  = threadIdx.x;
    const int rank = blockIdx.x % CL;
    const int bg   = blockIdx.x / CL;
    const int C0   = rank * NC;
    const int B0   = bg * NB;

    // compute-role: 128 column-threads x 4 k-slices (warp-uniform ksub)
    const int ct   = tid & 127;
    const int ksub = tid >> 7;
    const int cc   = C0 + ct;
    const int kb   = ksub * (H_ / KS);    // 128 wrec k start
    const int ib   = ksub * (I_ / KS);    // 16 wi k start

    // finalize-role (tid < 256): batch fb, column fc
    const int fb = tid >> 7;
    const int fc = tid & 127;
    const int gb = B0 + fb;
    const int gc = C0 + fc;

    // -------- weights: 44 pairs in regs, 28 pairs in smem -------------------
    unsigned long long wreg[NREG];        // 88 registers
#pragma unroll
    for (int pp = 0; pp < NREG; pp++) {
        int k0 = kb + 2 * pp;
        float a = fabsf(wrec[(size_t)k0 * H_ + cc]) * wrec_mask[(size_t)k0 * H_ + cc];
        float b = fabsf(wrec[(size_t)(k0 + 1) * H_ + cc]) * wrec_mask[(size_t)(k0 + 1) * H_ + cc];
        wreg[pp] = pk2(a, b);
    }
    for (int j = 0; j < 20; j++) {        // wrec pairs 44..63
        int k0 = kb + 2 * (NREG + j);
        float a = fabsf(wrec[(size_t)k0 * H_ + cc]) * wrec_mask[(size_t)k0 * H_ + cc];
        float b = fabsf(wrec[(size_t)(k0 + 1) * H_ + cc]) * wrec_mask[(size_t)(k0 + 1) * H_ + cc];
        s_w[j * TPB + tid] = pk2(a, b);
    }
    for (int j = 0; j < 8; j++) {         // wi pairs 0..7
        int i0 = ib + 2 * j;
        float a = wi[(size_t)i0 * H_ + cc] * si[i0] * wi_mask[(size_t)i0 * H_ + cc];
        float b = wi[(size_t)(i0 + 1) * H_ + cc] * si[i0 + 1] * wi_mask[(size_t)(i0 + 1) * H_ + cc];
        s_w[(20 + j) * TPB + tid] = pk2(a, b);
    }

    const uint32_t s_op_u32 = smem_u32(s_op);
    const uint32_t mbar_u32 = smem_u32(smem + OFF_MBAR);
    // my (even-col) send destination byte offset within the h region
    const uint32_t dst_off = (uint32_t)(((gc >> 1) * 4 + fb * 2) * 4);

    const float fbias = (tid < 256) ? bias[gc] : 0.f;

    // incremented pointers
    const float* nz_p = noise + ((size_t)gb * T_) * H_ + gc;            // += H_
    const int xb = (tid >> 5) & 1, xi = (tid & 31) * 2;                 // tid 256..319
    const float* x_p  = input + ((size_t)(B0 + xb) * T_) * I_ + xi;     // += I_
    float*       tr_p = traj + ((size_t)gb * (T_ + 1)) * H_ + gc;       // += H_

    // -------- init ----------------------------------------------------------
    if (tid == 0) {
        mbar_init(mbar_u32, MBCOUNT);
        mbar_init(mbar_u32 + 8, MBCOUNT);
    }
    float h_prev = 0.f;
    if (tid < 256) {
        h_prev = h0[gc];
        *tr_p = h_prev;
        tr_p += H_;
    }
    // stage relu(h0) into buffer 0 (element e encodes (pair,b,half) directly)
#pragma unroll
    for (int q = 0; q < 2; q++) {
        int e = tid * 2 + q;              // [0,1024)
        int k = (e >> 2) * 2 + (e & 1);
        s_op[e] = fmaxf(h0[k], 0.f);
    }
    if (tid >= 256 && tid < 320) {        // stage x_0
        float2 xv = *(const float2*)x_p;
        *(float2*)&s_op[XBASE + (xi >> 1) * 4 + xb * 2] = xv;
        x_p += I_;
    }
    __syncthreads();
    cluster_sync();   // mbarriers + buffer0 + smem weights visible

    int p = 0;
    uint32_t ph0 = 0, ph1 = 0;
    for (int t = 0; t < T_; t++) {
        const int pn = p ^ 1;

        // ---- prefetch -------------------------------------------------------
        float nz = 0.f;
        if (tid < 256) { nz = *nz_p; nz_p += H_; }
        float2 xnext = make_float2(0.f, 0.f);
        if (tid >= 256 && tid < 320 && t + 1 < T_) {
            xnext = *(const float2*)x_p; x_p += I_;
        }

        if (tid == 0 && t + 1 < T_)
            mbar_expect_tx(mbar_u32 + 8u * pn, EXPBYTES);

        // ---- wait for this step's operands (h blocks + x staged) -----------
        if (t > 0) {
            if (p == 0) { mbar_wait(mbar_u32, ph0);     ph0 ^= 1; }
            else        { mbar_wait(mbar_u32 + 8, ph1); ph1 ^= 1; }
        }

        // ---- matmul: 72 k-pairs x 2 batches, 1 column ----------------------
        const float* ob  = s_op + p * OPF + (ksub << 8);      // wrec operands
        const float* obx = s_op + p * OPF + XBASE + (ksub << 5); // wi operands
        const unsigned long long* swp = s_w + tid;

        unsigned long long a0 = 0ULL, a1 = 0ULL;
#pragma unroll
        for (int pp = 0; pp < NREG; pp++) {
            ulonglong2 v = *(const ulonglong2*)&ob[pp << 2];
            ffma2(a0, v.x, wreg[pp]);
            ffma2(a1, v.y, wreg[pp]);
        }
#pragma unroll
        for (int j = 0; j < 20; j++) {
            unsigned long long w = swp[j * TPB];
            ulonglong2 v = *(const ulonglong2*)&ob[(NREG + j) << 2];
            ffma2(a0, v.x, w);
            ffma2(a1, v.y, w);
        }
#pragma unroll
        for (int j = 0; j < 8; j++) {
            unsigned long long w = swp[(20 + j) * TPB];
            ulonglong2 v = *(const ulonglong2*)&obx[j << 2];
            ffma2(a0, v.x, w);
            ffma2(a1, v.y, w);
        }
        // collapse packed halves -> f32 partials (double-buffered by p)
        float* rd = s_rd + ((p * NB) * KS + ksub) * NC + ct;
        rd[0]            = lo32(a0) + hi32(a0);
        rd[KS * NC]      = lo32(a1) + hi32(a1);

        // stage x_{t+1} + arrive on next buffer's barrier
        if (tid >= 256 && tid < 320 && t + 1 < T_) {
            *(float2*)&s_op[pn * OPF + XBASE + (xi >> 1) * 4 + xb * 2] = xnext;
            mbar_arrive(mbar_u32 + 8u * pn);
        }
        __syncthreads();                  // partials ready for finalize

        // ---- finalize: sum 4 slices, h update, traj, 4 async sends ----------
        if (tid < 256) {
            const float* rb = s_rd + ((p * NB + fb) * KS) * NC + fc;
            float s = rb[0] + rb[NC] + rb[2 * NC] + rb[3 * NC];

            float h_new = h_prev + NSTD * nz + ALPHA * (-h_prev + s + fbias);
            float rv = fmaxf(h_new, 0.f);
            float rv_hi = __shfl_down_sync(0xffffffffu, rv, 1);
            float hn_hi = __shfl_down_sync(0xffffffffu, h_new, 1);
            if ((fc & 1) == 0) {
                if (t + 1 < T_) {
                    unsigned long long hv = pk2(rv, rv_hi);
                    uint32_t doff = (uint32_t)pn * (OPF * 4) + dst_off;
                    uint32_t moff = 8u * (uint32_t)pn;
#pragma unroll
                    for (int r = 0; r < CL; r++) {
                        uint32_t ra = mapa_rank(s_op_u32, (uint32_t)r) + doff;
                        uint32_t rm = mapa_rank(mbar_u32, (uint32_t)r) + moff;
                        st_async_b64(ra, hv, rm);
                    }
                }
                *(float2*)tr_p = make_float2(h_new, hn_hi);
            }
            tr_p += H_;
            h_prev = h_new;
        }

        p = pn;
    }

    cluster_sync();   // no CTA exits while peers' st.async may target it
}

// output pass: out[b,t,o] = relu(traj[b,t+1,:]) @ wo_eff
extern "C" __global__ void __launch_bounds__(256)
rnn_out(const float* __restrict__ traj, const float* __restrict__ wo,
        const float* __restrict__ so, const float* __restrict__ wo_mask,
        float* __restrict__ out)
{
    __shared__ float s_wo[O_][H_];
    const int tid = threadIdx.x;
    for (int i = tid; i < H_ * O_; i += 256) {
        int c = i / O_, o = i % O_;
        s_wo[o][c] = wo[i] * so[o] * wo_mask[i];
    }
    __syncthreads();

    const int warp = tid >> 5, lane = tid & 31;
    const size_t row = (size_t)blockIdx.x * 8 + warp;   // b*T + t
    const int b = (int)(row >> 10);
    const int t = (int)(row & 1023);
    const float* tp = traj + ((size_t)b * (T_ + 1) + t + 1) * H_;

    float acc[O_];
#pragma unroll
    for (int o = 0; o < O_; o++) acc[o] = 0.f;

    for (int ccb = 0; ccb < H_; ccb += 32) {
        float r = fmaxf(tp[ccb + lane], 0.f);
#pragma unroll
        for (int o = 0; o < O_; o++) acc[o] += r * s_wo[o][ccb + lane];
    }
#pragma unroll
    for (int off = 16; off; off >>= 1)
#pragma unroll
        for (int o = 0; o < O_; o++)
            acc[o] += __shfl_down_sync(0xffffffffu, acc[o], off);
    if (lane == 0) {
#pragma unroll
        for (int o = 0; o < O_; o++) out[row * O_ + o] = acc[o];
    }
}

extern "C" void kernel_launch(void* const* d_in, const int* in_sizes, int n_in,
                              void* d_out, int out_size)
{
    (void)in_sizes; (void)n_in; (void)out_size;
    const float* input = (const float*)d_in[0];
    const float* noise = (const float*)d_in[1];
    const float* wi    = (const float*)d_in[2];
    const float* si    = (const float*)d_in[3];
    const float* wrec  = (const float*)d_in[4];
    const float* bias  = (const float*)d_in[5];
    const float* wo    = (const float*)d_in[6];
    const float* so    = (const float*)d_in[7];
    const float* wim   = (const float*)d_in[8];
    const float* wrm   = (const float*)d_in[9];
    const float* wom   = (const float*)d_in[10];
    const float* h0    = (const float*)d_in[11];

    float* out  = (float*)d_out;
    float* traj = out + (size_t)B_ * T_ * O_;   // [B, T+1, H] after [B, T, O]

    cudaFuncSetAttribute(rnn_main,
                         cudaFuncAttributeMaxDynamicSharedMemorySize, SMEM_TOTAL);

    // 3 no-op launches: aim ncu capture (launch idx 3) at rnn_main
    for (int i = 0; i < 3; i++) knop<<<1, 32>>>();

    rnn_main<<<GRID, TPB, SMEM_TOTAL>>>(input, noise, wi, si, wrec, bias,
                                        wim, wrm, h0, traj);
    rnn_out<<<(B_ * T_) / 8, 256>>>(traj, wo, so, wom, out);
}